// round 1
// baseline (speedup 1.0000x reference)
#include <cuda_runtime.h>
#include <math.h>

// Problem constants
#define B_    16
#define N_    4096
#define CIN   256
#define CH_   256
#define DW    512     // RADIX * CH
#define IN_   128     // inter channels

// attens scratch: [B][2][256] flattened as [b*512 + d] where d<256 -> r=0, d>=256 -> r=1
__device__ float g_attw[B_ * DW];

// ---------------------------------------------------------------------------
// Kernel 1: attention path. Only rows n=0 and n=1024 of each batch matter
// (rSoftMax keeps only the first RADIX*CH elements of the flattened softmax).
// attens[b,0,c] = sigmoid(atten[b,0,c]     - atten[b,1024,c])
// attens[b,1,c] = sigmoid(atten[b,0,256+c] - atten[b,1024,256+c])
// b_fc2 cancels in the difference.
// ---------------------------------------------------------------------------
__global__ __launch_bounds__(256) void atten_kernel(
    const float* __restrict__ x,
    const float* __restrict__ w_conv,
    const float* __restrict__ b_conv,
    const float* __restrict__ w_fc1,
    const float* __restrict__ b_fc1,
    const float* __restrict__ w_fc2)
{
    const int b   = blockIdx.x;
    const int tid = threadIdx.x;

    __shared__ float xs0[CIN], xs1[CIN];
    __shared__ float h0[DW], h1[DW];
    __shared__ float gap0[CH_], gap1[CH_];
    __shared__ float g0[IN_], g1[IN_], gd[IN_];

    xs0[tid] = x[(b * N_ + 0)    * CIN + tid];
    xs1[tid] = x[(b * N_ + 1024) * CIN + tid];
    __syncthreads();

    // h rows for n=0 and n=1024 (relu(x @ w_conv^T + b_conv))
    #pragma unroll
    for (int dd = 0; dd < 2; dd++) {
        const int d = tid + dd * 256;
        const float4* w = (const float4*)(w_conv + d * CIN);
        float s0 = 0.f, s1 = 0.f;
        #pragma unroll 8
        for (int k4 = 0; k4 < CIN / 4; k4++) {
            float4 wv = w[k4];
            float4 x0 = ((const float4*)xs0)[k4];
            float4 x1 = ((const float4*)xs1)[k4];
            s0 += wv.x * x0.x + wv.y * x0.y + wv.z * x0.z + wv.w * x0.w;
            s1 += wv.x * x1.x + wv.y * x1.y + wv.z * x1.z + wv.w * x1.w;
        }
        const float bb = b_conv[d];
        h0[d] = fmaxf(s0 + bb, 0.f);
        h1[d] = fmaxf(s1 + bb, 0.f);
    }
    __syncthreads();

    // radix-split sum
    gap0[tid] = h0[tid] + h0[tid + CH_];
    gap1[tid] = h1[tid] + h1[tid + CH_];
    __syncthreads();

    // g = relu(gap @ w_fc1^T + b_fc1): threads 0..127 -> g0, 128..255 -> g1
    {
        const int i = tid & 127;
        const float* gp = (tid < 128) ? gap0 : gap1;
        const float4* w = (const float4*)(w_fc1 + i * CH_);
        float s = 0.f;
        #pragma unroll 8
        for (int k4 = 0; k4 < CH_ / 4; k4++) {
            float4 wv = w[k4];
            float4 gv = ((const float4*)gp)[k4];
            s += wv.x * gv.x + wv.y * gv.y + wv.z * gv.z + wv.w * gv.w;
        }
        s = fmaxf(s + b_fc1[i], 0.f);
        if (tid < 128) g0[i] = s; else g1[i] = s;
    }
    __syncthreads();
    if (tid < IN_) gd[tid] = g0[tid] - g1[tid];
    __syncthreads();

    // delta[d] = (g0 - g1) . w_fc2[d], attens = sigmoid(delta)
    #pragma unroll
    for (int dd = 0; dd < 2; dd++) {
        const int d = tid + dd * 256;
        const float4* w = (const float4*)(w_fc2 + d * IN_);
        float s = 0.f;
        #pragma unroll 8
        for (int k4 = 0; k4 < IN_ / 4; k4++) {
            float4 wv = w[k4];
            float4 gv = ((const float4*)gd)[k4];
            s += wv.x * gv.x + wv.y * gv.y + wv.z * gv.z + wv.w * gv.w;
        }
        g_attw[b * DW + d] = 1.f / (1.f + expf(-s));
    }
}

// ---------------------------------------------------------------------------
// Kernel 2: fused main path.
// For all 65536 rows: h[d] = relu(x . w_conv[d] + b_conv[d]) for d in [0,512),
// out[n,b,c] = attw[b,c]*h[c] + attw[b,256+c]*h[256+c], output layout [N,B,CH].
// GEMM tiling: BM=64 rows x 512 cols, BK=16, 512 threads, 8x8 thread tile
// (thread cols are a (c, c+256) pair-group so the combine is local).
// ---------------------------------------------------------------------------
#define BM   64
#define BK   16
#define BSLD 516   // padded Bs row to kill transpose-store bank conflicts

__global__ __launch_bounds__(512, 1) void main_kernel(
    const float* __restrict__ x,
    const float* __restrict__ w_conv,
    const float* __restrict__ b_conv,
    float* __restrict__ out)
{
    __shared__ float As[BK][BM];     // 4 KB   As[k][m]
    __shared__ float Bs[BK][BSLD];   // 33 KB  Bs[k][d]

    const int tid  = threadIdx.x;
    const int m0   = blockIdx.x * BM;       // 64 rows per block, same batch
    const int bb   = m0 >> 12;              // batch = m0 / 4096
    const int n0   = m0 & (N_ - 1);
    const int trow = tid >> 6;               // 0..7
    const int tcol = tid & 63;               // 0..63

    float acc[8][8];
    #pragma unroll
    for (int i = 0; i < 8; i++)
        #pragma unroll
        for (int j = 0; j < 8; j++) acc[i][j] = 0.f;

    // register prefetch buffers
    float4 aReg = make_float4(0.f, 0.f, 0.f, 0.f);
    float4 bReg[4];

    const int aM = tid >> 2;           // 0..127 (only tid<256 loads A)
    const int aK = (tid & 3) << 2;     // 0,4,8,12
    const int bD = tid >> 2;           // 0..127 (+ p*128)
    const int bK = (tid & 3) << 2;

    // prologue loads for ks = 0
    if (tid < 256)
        aReg = *(const float4*)&x[(size_t)(m0 + aM) * CIN + aK];
    #pragma unroll
    for (int p = 0; p < 4; p++)
        bReg[p] = *(const float4*)&w_conv[(size_t)(bD + p * 128) * CIN + bK];

    for (int ks = 0; ks < CIN; ks += BK) {
        __syncthreads();   // previous compute done reading smem
        if (tid < 256) {
            As[aK + 0][aM] = aReg.x;
            As[aK + 1][aM] = aReg.y;
            As[aK + 2][aM] = aReg.z;
            As[aK + 3][aM] = aReg.w;
        }
        #pragma unroll
        for (int p = 0; p < 4; p++) {
            const int d = bD + p * 128;
            Bs[bK + 0][d] = bReg[p].x;
            Bs[bK + 1][d] = bReg[p].y;
            Bs[bK + 2][d] = bReg[p].z;
            Bs[bK + 3][d] = bReg[p].w;
        }
        __syncthreads();

        // prefetch next k-slab while computing this one
        if (ks + BK < CIN) {
            const int kn = ks + BK;
            if (tid < 256)
                aReg = *(const float4*)&x[(size_t)(m0 + aM) * CIN + kn + aK];
            #pragma unroll
            for (int p = 0; p < 4; p++)
                bReg[p] = *(const float4*)&w_conv[(size_t)(bD + p * 128) * CIN + kn + bK];
        }

        #pragma unroll
        for (int k = 0; k < BK; k++) {
            float a[8], bf[8];
            *(float4*)&a[0]  = *(const float4*)&As[k][trow * 8];
            *(float4*)&a[4]  = *(const float4*)&As[k][trow * 8 + 4];
            *(float4*)&bf[0] = *(const float4*)&Bs[k][tcol * 4];         // cols c..c+3
            *(float4*)&bf[4] = *(const float4*)&Bs[k][tcol * 4 + 256];   // cols c+256..
            #pragma unroll
            for (int i = 0; i < 8; i++)
                #pragma unroll
                for (int j = 0; j < 8; j++)
                    acc[i][j] += a[i] * bf[j];
        }
    }

    // epilogue: bias + relu + sigmoid-weighted radix combine, write [N,B,CH]
    const int cbase = tcol * 4;
    float a0[4], a1[4], bias0[4], bias1[4];
    #pragma unroll
    for (int j = 0; j < 4; j++) {
        a0[j]    = g_attw[bb * DW + cbase + j];
        a1[j]    = g_attw[bb * DW + 256 + cbase + j];
        bias0[j] = b_conv[cbase + j];
        bias1[j] = b_conv[256 + cbase + j];
    }
    #pragma unroll
    for (int i = 0; i < 8; i++) {
        const int n = n0 + trow * 8 + i;
        float4 o;
        o.x = a0[0] * fmaxf(acc[i][0] + bias0[0], 0.f) + a1[0] * fmaxf(acc[i][4] + bias1[0], 0.f);
        o.y = a0[1] * fmaxf(acc[i][1] + bias0[1], 0.f) + a1[1] * fmaxf(acc[i][5] + bias1[1], 0.f);
        o.z = a0[2] * fmaxf(acc[i][2] + bias0[2], 0.f) + a1[2] * fmaxf(acc[i][6] + bias1[2], 0.f);
        o.w = a0[3] * fmaxf(acc[i][3] + bias0[3], 0.f) + a1[3] * fmaxf(acc[i][7] + bias1[3], 0.f);
        *(float4*)&out[((size_t)n * B_ + bb) * CH_ + cbase] = o;
    }
}

extern "C" void kernel_launch(void* const* d_in, const int* in_sizes, int n_in,
                              void* d_out, int out_size) {
    const float* x      = (const float*)d_in[0];
    const float* w_conv = (const float*)d_in[1];
    const float* b_conv = (const float*)d_in[2];
    const float* w_fc1  = (const float*)d_in[3];
    const float* b_fc1  = (const float*)d_in[4];
    const float* w_fc2  = (const float*)d_in[5];
    // d_in[6] = b_fc2: cancels in the softmax-pair difference, unused.
    float* out = (float*)d_out;

    atten_kernel<<<B_, 256>>>(x, w_conv, b_conv, w_fc1, b_fc1, w_fc2);
    main_kernel<<<(B_ * N_) / BM, 512>>>(x, w_conv, b_conv, out);
}

// round 3
// speedup vs baseline: 2.2010x; 2.2010x over previous
#include <cuda_runtime.h>
#include <cuda_bf16.h>
#include <cstdint>
#include <math.h>

#define B_    16
#define N_    4096
#define CIN   256
#define CH_   256
#define DW    512
#define IN_   128

// Feature detection: tcgen05 asm only compiles under an 'a'-suffixed target.
#if defined(__CUDA_ARCH_FEAT_SM103_ALL) || defined(__CUDA_ARCH_FEAT_SM100_ALL) || defined(__CUDA_ARCH_FEAT_SM101_ALL)
#define USE_TCGEN05 1
#else
#define USE_TCGEN05 0
#endif

// -------------------- device scratch --------------------
__device__ float g_attw[B_ * DW];
__device__ __nv_bfloat16 g_x2[(size_t)B_ * N_ * 512];   // [65536][512]  hi|lo
__device__ __nv_bfloat16 g_w3[512 * 768];               // [512][768]    whi|whi|wlo

// -------------------- PTX helpers (only instantiated when used) ------------
__device__ __forceinline__ uint32_t smem_u32(const void* p) {
    uint32_t a;
    asm("{ .reg .u64 t; cvta.to.shared.u64 t, %1; cvt.u32.u64 %0, t; }" : "=r"(a) : "l"(p));
    return a;
}
__device__ __forceinline__ uint32_t elect_one() {
    uint32_t pred;
    asm volatile("{\n\t.reg .pred p;\n\telect.sync _|p, 0xFFFFFFFF;\n\tselp.b32 %0, 1, 0, p;\n\t}" : "=r"(pred));
    return pred;
}
#define TCGEN05_ALLOC(sa, n) \
    asm volatile("tcgen05.alloc.cta_group::1.sync.aligned.shared::cta.b32 [%0], %1;" :: "r"((uint32_t)(sa)), "r"((uint32_t)(n)) : "memory")
#define TCGEN05_DEALLOC(t, n) \
    asm volatile("tcgen05.dealloc.cta_group::1.sync.aligned.b32 %0, %1;" :: "r"(t), "r"((uint32_t)(n)))
#define TCGEN05_RELINQ() \
    asm volatile("tcgen05.relinquish_alloc_permit.cta_group::1.sync.aligned;")
#define TCGEN05_COMMIT(mb) \
    asm volatile("tcgen05.commit.cta_group::1.mbarrier::arrive::one.shared::cluster.b64 [%0];" :: "r"((uint32_t)(mb)) : "memory")
#define TCGEN05_WAIT_LD() asm volatile("tcgen05.wait::ld.sync.aligned;" ::: "memory")
#define TCGEN05_FENCE_AFTER() asm volatile("tcgen05.fence::after_thread_sync;" ::: "memory")
#define MBARRIER_INIT(mb, cnt) \
    asm volatile("mbarrier.init.shared.b64 [%0], %1;" :: "r"((uint32_t)(mb)), "r"((uint32_t)(cnt)) : "memory")
#define MBARRIER_WAIT_PARITY(mb, ph) do { \
    uint32_t _m = (uint32_t)(mb), _p = (uint32_t)(ph), _d; \
    asm volatile("{\n\t.reg .pred p;\n\tmbarrier.try_wait.parity.acquire.cta.shared::cta.b64 p, [%1], %2;\n\tselp.b32 %0, 1, 0, p;\n\t}" \
        : "=r"(_d) : "r"(_m), "r"(_p) : "memory"); \
    if (!_d) { \
        asm volatile("{\n\t.reg .pred P1;\n\tWL_%=:\n\tmbarrier.try_wait.parity.acquire.cta.shared::cta.b64 P1, [%0], %1, 0x989680;\n\t@P1 bra.uni WD_%=;\n\tbra.uni WL_%=;\n\tWD_%=:\n\t}" \
            :: "r"(_m), "r"(_p) : "memory"); \
    } \
} while (0)
#define TCGEN05_LD_X32(r, ta) \
    asm volatile("tcgen05.ld.sync.aligned.32x32b.x32.b32 " \
        "{%0,%1,%2,%3,%4,%5,%6,%7,%8,%9,%10,%11,%12,%13,%14,%15," \
        "%16,%17,%18,%19,%20,%21,%22,%23,%24,%25,%26,%27,%28,%29,%30,%31}, [%32];" \
        : "=r"((r)[0]),"=r"((r)[1]),"=r"((r)[2]),"=r"((r)[3]),"=r"((r)[4]),"=r"((r)[5]),"=r"((r)[6]),"=r"((r)[7]), \
          "=r"((r)[8]),"=r"((r)[9]),"=r"((r)[10]),"=r"((r)[11]),"=r"((r)[12]),"=r"((r)[13]),"=r"((r)[14]),"=r"((r)[15]), \
          "=r"((r)[16]),"=r"((r)[17]),"=r"((r)[18]),"=r"((r)[19]),"=r"((r)[20]),"=r"((r)[21]),"=r"((r)[22]),"=r"((r)[23]), \
          "=r"((r)[24]),"=r"((r)[25]),"=r"((r)[26]),"=r"((r)[27]),"=r"((r)[28]),"=r"((r)[29]),"=r"((r)[30]),"=r"((r)[31]) \
        : "r"(ta))

static constexpr uint64_t SMEM_DESC_BASE_SW128 =
    (uint64_t(2) << 61) | (uint64_t(1) << 46) | (uint64_t(64) << 32) | (uint64_t(1) << 16);
#define MAKE_SMEM_DESC(a) (SMEM_DESC_BASE_SW128 | ((uint64_t)((a) >> 4) & 0x3FFF))

#if USE_TCGEN05
// SS-mode cg1 bf16 MMA: D[128,256] += A[128,16] * B[256,16]^T
__device__ __forceinline__ void mma_f16_ss(uint32_t d, uint64_t ad, uint64_t bd, uint32_t idesc, bool acc) {
    uint32_t en = acc ? 1u : 0u;
    asm volatile(
        "{\n\t.reg .pred p;\n\tsetp.ne.u32 p, %5, 0;\n\t"
        "tcgen05.mma.cta_group::1.kind::f16 [%0], %1, %2, %3, {%4, %4, %4, %4}, p;\n\t}"
        :: "r"(d), "l"(ad), "l"(bd), "r"(idesc), "r"(0u), "r"(en) : "memory");
}
#endif
// idesc: F32 accum, BF16 x BF16, M=128, N=256
static constexpr uint32_t IDESC =
    (1u << 4) | (1u << 7) | (1u << 10) | ((256u / 8u) << 17) | ((128u / 16u) << 24);

// ---------------------------------------------------------------------------
// Kernel 1: attention path (fp32, exact). Only rows n=0 / n=1024 per batch
// survive the rSoftMax slice; b_fc2 cancels in the pair difference.
// ---------------------------------------------------------------------------
__global__ __launch_bounds__(256) void atten_kernel(
    const float* __restrict__ x,
    const float* __restrict__ w_conv,
    const float* __restrict__ b_conv,
    const float* __restrict__ w_fc1,
    const float* __restrict__ b_fc1,
    const float* __restrict__ w_fc2)
{
    const int b   = blockIdx.x;
    const int tid = threadIdx.x;

    __shared__ float xs0[CIN], xs1[CIN];
    __shared__ float h0[DW], h1[DW];
    __shared__ float gap0[CH_], gap1[CH_];
    __shared__ float g0[IN_], g1[IN_], gd[IN_];

    xs0[tid] = x[(b * N_ + 0)    * CIN + tid];
    xs1[tid] = x[(b * N_ + 1024) * CIN + tid];
    __syncthreads();

    #pragma unroll
    for (int dd = 0; dd < 2; dd++) {
        const int d = tid + dd * 256;
        const float4* w = (const float4*)(w_conv + d * CIN);
        float s0 = 0.f, s1 = 0.f;
        #pragma unroll 8
        for (int k4 = 0; k4 < CIN / 4; k4++) {
            float4 wv = w[k4];
            float4 x0 = ((const float4*)xs0)[k4];
            float4 x1 = ((const float4*)xs1)[k4];
            s0 += wv.x * x0.x + wv.y * x0.y + wv.z * x0.z + wv.w * x0.w;
            s1 += wv.x * x1.x + wv.y * x1.y + wv.z * x1.z + wv.w * x1.w;
        }
        const float bb = b_conv[d];
        h0[d] = fmaxf(s0 + bb, 0.f);
        h1[d] = fmaxf(s1 + bb, 0.f);
    }
    __syncthreads();

    gap0[tid] = h0[tid] + h0[tid + CH_];
    gap1[tid] = h1[tid] + h1[tid + CH_];
    __syncthreads();

    {
        const int i = tid & 127;
        const float* gp = (tid < 128) ? gap0 : gap1;
        const float4* w = (const float4*)(w_fc1 + i * CH_);
        float s = 0.f;
        #pragma unroll 8
        for (int k4 = 0; k4 < CH_ / 4; k4++) {
            float4 wv = w[k4];
            float4 gv = ((const float4*)gp)[k4];
            s += wv.x * gv.x + wv.y * gv.y + wv.z * gv.z + wv.w * gv.w;
        }
        s = fmaxf(s + b_fc1[i], 0.f);
        if (tid < 128) g0[i] = s; else g1[i] = s;
    }
    __syncthreads();
    if (tid < IN_) gd[tid] = g0[tid] - g1[tid];
    __syncthreads();

    #pragma unroll
    for (int dd = 0; dd < 2; dd++) {
        const int d = tid + dd * 256;
        const float4* w = (const float4*)(w_fc2 + d * IN_);
        float s = 0.f;
        #pragma unroll 8
        for (int k4 = 0; k4 < IN_ / 4; k4++) {
            float4 wv = w[k4];
            float4 gv = ((const float4*)gd)[k4];
            s += wv.x * gv.x + wv.y * gv.y + wv.z * gv.z + wv.w * gv.w;
        }
        g_attw[b * DW + d] = 1.f / (1.f + expf(-s));
    }
}

// ---------------------------------------------------------------------------
// Kernel 2a: x -> bf16 hi|lo split, g_x2[row][0:256)=hi, [256:512)=lo
// ---------------------------------------------------------------------------
__global__ __launch_bounds__(512) void prep_x(const float* __restrict__ x) {
    size_t gi = ((size_t)blockIdx.x * 512 + threadIdx.x) * 4;
    float4 v = *(const float4*)(x + gi);
    size_t row = gi >> 8;
    int k = (int)(gi & 255);
    __nv_bfloat162 h0 = __floats2bfloat162_rn(v.x, v.y);
    __nv_bfloat162 h1 = __floats2bfloat162_rn(v.z, v.w);
    __nv_bfloat162 l0 = __floats2bfloat162_rn(v.x - __bfloat162float(h0.x),
                                              v.y - __bfloat162float(h0.y));
    __nv_bfloat162 l1 = __floats2bfloat162_rn(v.z - __bfloat162float(h1.x),
                                              v.w - __bfloat162float(h1.y));
    __nv_bfloat16* base = g_x2 + row * 512;
    *(__nv_bfloat162*)(base + k)           = h0;
    *(__nv_bfloat162*)(base + k + 2)       = h1;
    *(__nv_bfloat162*)(base + 256 + k)     = l0;
    *(__nv_bfloat162*)(base + 256 + k + 2) = l1;
}

// ---------------------------------------------------------------------------
// Kernel 2b: w_conv -> g_w3[d][0:256)=whi, [256:512)=whi, [512:768)=wlo
// ---------------------------------------------------------------------------
__global__ __launch_bounds__(256) void prep_w(const float* __restrict__ w) {
    int gi = (blockIdx.x * 256 + threadIdx.x) * 4;
    float4 v = *(const float4*)(w + gi);
    int d = gi >> 8, k = gi & 255;
    __nv_bfloat162 h0 = __floats2bfloat162_rn(v.x, v.y);
    __nv_bfloat162 h1 = __floats2bfloat162_rn(v.z, v.w);
    __nv_bfloat162 l0 = __floats2bfloat162_rn(v.x - __bfloat162float(h0.x),
                                              v.y - __bfloat162float(h0.y));
    __nv_bfloat162 l1 = __floats2bfloat162_rn(v.z - __bfloat162float(h1.x),
                                              v.w - __bfloat162float(h1.y));
    __nv_bfloat16* base = g_w3 + d * 768;
    *(__nv_bfloat162*)(base + k)           = h0;
    *(__nv_bfloat162*)(base + k + 2)       = h1;
    *(__nv_bfloat162*)(base + 256 + k)     = h0;
    *(__nv_bfloat162*)(base + 256 + k + 2) = h1;
    *(__nv_bfloat162*)(base + 512 + k)     = l0;
    *(__nv_bfloat162*)(base + 512 + k + 2) = l1;
}

// ---------------------------------------------------------------------------
// Kernel 3: GEMM + fused epilogue (bias+ReLU+sigmoid-weighted radix combine).
// tcgen05 path on sm_103a-featured pass; fp32 FFMA fallback otherwise.
// Grid: 512 CTAs x 128 rows, 512 threads, SMEM_TOTAL dynamic smem.
// ---------------------------------------------------------------------------
#define KC       64
#define NCHUNKS  12
#define SMEM_A_OFF   1024
#define SMEM_W_OFF   (1024 + 2 * 16384)
#define SMEM_TOTAL   (1024 + 2 * 16384 + 2 * 65536)

__global__ __launch_bounds__(512, 1)
void gemm_kernel(const float* __restrict__ x,
                 const float* __restrict__ w_conv,
                 const float* __restrict__ b_conv,
                 float* __restrict__ out)
{
    extern __shared__ __align__(1024) char smem[];
    const int tid = threadIdx.x;
    const int m0  = blockIdx.x * 128;
    const int bb  = m0 >> 12;
    const int n0  = m0 & (N_ - 1);

#if USE_TCGEN05
    const uint32_t sb = smem_u32(smem);
    const int wid = tid >> 5, lid = tid & 31;
    const uint32_t MB0 = sb + 8, MB1 = sb + 16;

    if (wid == 0) TCGEN05_ALLOC(sb, 512);
    if (tid == 0) { MBARRIER_INIT(MB0, 1); MBARRIER_INIT(MB1, 1); }
    __syncthreads();
    uint32_t tmem;
    asm volatile("ld.shared.b32 %0, [%1];" : "=r"(tmem) : "r"(sb));

    const int j  = tid & 7;     // 16B unit within 128B row
    const int r0 = tid >> 3;    // 0..63
    int ph0 = 0, ph1 = 0;

    for (int c = 0; c < NCHUNKS; c++) {
        const int p = c & 1;
        if (c >= 2) {
            if (p == 0) { MBARRIER_WAIT_PARITY(MB0, ph0); ph0 ^= 1; }
            else        { MBARRIER_WAIT_PARITY(MB1, ph1); ph1 ^= 1; }
        }
        const int ka = (c < 8) ? c * KC : (c - 8) * KC;  // x2 k-offset (bf16)
        const int kw = c * KC;                           // w3 k-offset
        const uint32_t abuf = sb + SMEM_A_OFF + p * 16384;
        const uint32_t wbuf = sb + SMEM_W_OFF + p * 65536;

        // A tile: 128 rows x 64 bf16, SW128-swizzled
        #pragma unroll
        for (int i = 0; i < 2; i++) {
            const int r = r0 + 64 * i;
            uint4 v = *(const uint4*)&g_x2[(size_t)(m0 + r) * 512 + ka + j * 8];
            uint32_t dst = abuf + r * 128 + ((j ^ (r & 7)) << 4);
            asm volatile("st.shared.v4.b32 [%0], {%1,%2,%3,%4};"
                :: "r"(dst), "r"(v.x), "r"(v.y), "r"(v.z), "r"(v.w) : "memory");
        }
        // W tile: 512 rows x 64 bf16, SW128-swizzled
        #pragma unroll
        for (int i = 0; i < 8; i++) {
            const int d = r0 + 64 * i;
            uint4 v = *(const uint4*)&g_w3[(size_t)d * 768 + kw + j * 8];
            uint32_t dst = wbuf + d * 128 + ((j ^ (d & 7)) << 4);
            asm volatile("st.shared.v4.b32 [%0], {%1,%2,%3,%4};"
                :: "r"(dst), "r"(v.x), "r"(v.y), "r"(v.z), "r"(v.w) : "memory");
        }
        asm volatile("fence.proxy.async.shared::cta;" ::: "memory");
        __syncthreads();

        if (wid == 0 && elect_one()) {
            uint64_t ad  = MAKE_SMEM_DESC(abuf);
            uint64_t wd0 = MAKE_SMEM_DESC(wbuf);
            uint64_t wd1 = MAKE_SMEM_DESC(wbuf + 256 * 128);
            #pragma unroll
            for (int k = 0; k < 4; k++) {
                const bool acc = !(c == 0 && k == 0);
                mma_f16_ss(tmem,       ad + k * 2, wd0 + k * 2, IDESC, acc);
                mma_f16_ss(tmem + 256, ad + k * 2, wd1 + k * 2, IDESC, acc);
            }
            TCGEN05_COMMIT(p ? MB1 : MB0);
        }
    }
    MBARRIER_WAIT_PARITY(MB0, ph0);
    MBARRIER_WAIT_PARITY(MB1, ph1);
    TCGEN05_FENCE_AFTER();

    if (tid < 128) {
        const int m = wid * 32 + lid;
        const int n = n0 + m;
        float* __restrict__ orow = out + ((size_t)n * B_ + bb) * CH_;
        const float* __restrict__ aw = g_attw + bb * DW;
        #pragma unroll 1
        for (int cc = 0; cc < 8; cc++) {
            uint32_t hr0[32], hr1[32];
            TCGEN05_LD_X32(hr0, tmem + cc * 32);
            TCGEN05_LD_X32(hr1, tmem + 256 + cc * 32);
            TCGEN05_WAIT_LD();
            #pragma unroll
            for (int q = 0; q < 8; q++) {
                const int ci = cc * 32 + q * 4;
                float4 b0 = *(const float4*)&b_conv[ci];
                float4 b1 = *(const float4*)&b_conv[256 + ci];
                float4 a0 = *(const float4*)&aw[ci];
                float4 a1 = *(const float4*)&aw[256 + ci];
                float4 o;
                o.x = a0.x * fmaxf(__uint_as_float(hr0[q*4+0]) + b0.x, 0.f)
                    + a1.x * fmaxf(__uint_as_float(hr1[q*4+0]) + b1.x, 0.f);
                o.y = a0.y * fmaxf(__uint_as_float(hr0[q*4+1]) + b0.y, 0.f)
                    + a1.y * fmaxf(__uint_as_float(hr1[q*4+1]) + b1.y, 0.f);
                o.z = a0.z * fmaxf(__uint_as_float(hr0[q*4+2]) + b0.z, 0.f)
                    + a1.z * fmaxf(__uint_as_float(hr1[q*4+2]) + b1.z, 0.f);
                o.w = a0.w * fmaxf(__uint_as_float(hr0[q*4+3]) + b0.w, 0.f)
                    + a1.w * fmaxf(__uint_as_float(hr1[q*4+3]) + b1.w, 0.f);
                *(float4*)(orow + ci) = o;
            }
        }
    }
    __syncthreads();
    if (wid == 0) { TCGEN05_DEALLOC(tmem, 512); TCGEN05_RELINQ(); }

#else  // ------------------- fp32 FFMA fallback (plain sm_103) --------------
    float (*As)[64]  = (float(*)[64])smem;
    float (*Bs)[516] = (float(*)[516])(smem + 16 * 64 * 4);

    const int trow = tid >> 6;   // 0..7
    const int tcol = tid & 63;   // 0..63
    const int aM = tid >> 2, aK = (tid & 3) << 2;
    const int bD = tid >> 2, bK = (tid & 3) << 2;

    for (int sub = 0; sub < 2; sub++) {
        const int ms = m0 + sub * 64;
        float acc[8][8];
        #pragma unroll
        for (int i = 0; i < 8; i++)
            #pragma unroll
            for (int jj = 0; jj < 8; jj++) acc[i][jj] = 0.f;

        float4 aReg = make_float4(0.f, 0.f, 0.f, 0.f);
        float4 bReg[4];
        if (tid < 256)
            aReg = *(const float4*)&x[(size_t)(ms + aM) * CIN + aK];
        #pragma unroll
        for (int p = 0; p < 4; p++)
            bReg[p] = *(const float4*)&w_conv[(size_t)(bD + p * 128) * CIN + bK];

        for (int ks = 0; ks < CIN; ks += 16) {
            __syncthreads();
            if (tid < 256) {
                As[aK + 0][aM] = aReg.x; As[aK + 1][aM] = aReg.y;
                As[aK + 2][aM] = aReg.z; As[aK + 3][aM] = aReg.w;
            }
            #pragma unroll
            for (int p = 0; p < 4; p++) {
                const int d = bD + p * 128;
                Bs[bK + 0][d] = bReg[p].x; Bs[bK + 1][d] = bReg[p].y;
                Bs[bK + 2][d] = bReg[p].z; Bs[bK + 3][d] = bReg[p].w;
            }
            __syncthreads();
            if (ks + 16 < CIN) {
                const int kn = ks + 16;
                if (tid < 256)
                    aReg = *(const float4*)&x[(size_t)(ms + aM) * CIN + kn + aK];
                #pragma unroll
                for (int p = 0; p < 4; p++)
                    bReg[p] = *(const float4*)&w_conv[(size_t)(bD + p * 128) * CIN + kn + bK];
            }
            #pragma unroll
            for (int k = 0; k < 16; k++) {
                float a[8], bf[8];
                *(float4*)&a[0]  = *(const float4*)&As[k][trow * 8];
                *(float4*)&a[4]  = *(const float4*)&As[k][trow * 8 + 4];
                *(float4*)&bf[0] = *(const float4*)&Bs[k][tcol * 4];
                *(float4*)&bf[4] = *(const float4*)&Bs[k][tcol * 4 + 256];
                #pragma unroll
                for (int i = 0; i < 8; i++)
                    #pragma unroll
                    for (int jj = 0; jj < 8; jj++)
                        acc[i][jj] += a[i] * bf[jj];
            }
        }
        __syncthreads();

        const int cbase = tcol * 4;
        float a0[4], a1[4], bias0[4], bias1[4];
        #pragma unroll
        for (int jj = 0; jj < 4; jj++) {
            a0[jj]    = g_attw[bb * DW + cbase + jj];
            a1[jj]    = g_attw[bb * DW + 256 + cbase + jj];
            bias0[jj] = b_conv[cbase + jj];
            bias1[jj] = b_conv[256 + cbase + jj];
        }
        #pragma unroll
        for (int i = 0; i < 8; i++) {
            const int n = n0 + sub * 64 + trow * 8 + i;
            float4 o;
            o.x = a0[0] * fmaxf(acc[i][0] + bias0[0], 0.f) + a1[0] * fmaxf(acc[i][4] + bias1[0], 0.f);
            o.y = a0[1] * fmaxf(acc[i][1] + bias0[1], 0.f) + a1[1] * fmaxf(acc[i][5] + bias1[1], 0.f);
            o.z = a0[2] * fmaxf(acc[i][2] + bias0[2], 0.f) + a1[2] * fmaxf(acc[i][6] + bias1[2], 0.f);
            o.w = a0[3] * fmaxf(acc[i][3] + bias0[3], 0.f) + a1[3] * fmaxf(acc[i][7] + bias1[3], 0.f);
            *(float4*)&out[((size_t)n * B_ + bb) * CH_ + cbase] = o;
        }
    }
#endif
}

extern "C" void kernel_launch(void* const* d_in, const int* in_sizes, int n_in,
                              void* d_out, int out_size) {
    const float* x      = (const float*)d_in[0];
    const float* w_conv = (const float*)d_in[1];
    const float* b_conv = (const float*)d_in[2];
    const float* w_fc1  = (const float*)d_in[3];
    const float* b_fc1  = (const float*)d_in[4];
    const float* w_fc2  = (const float*)d_in[5];
    // d_in[6] = b_fc2: cancels in the softmax-pair difference, unused.
    float* out = (float*)d_out;

    cudaFuncSetAttribute(gemm_kernel, cudaFuncAttributeMaxDynamicSharedMemorySize, SMEM_TOTAL);

    atten_kernel<<<B_, 256>>>(x, w_conv, b_conv, w_fc1, b_fc1, w_fc2);
    prep_x<<<(B_ * N_ * CIN) / (512 * 4), 512>>>(x);
    prep_w<<<(DW * CIN) / (256 * 4), 256>>>(w_conv);
    gemm_kernel<<<(B_ * N_) / 128, 512, SMEM_TOTAL>>>(x, w_conv, b_conv, out);
}

// round 4
// speedup vs baseline: 2.7660x; 1.2567x over previous
#include <cuda_runtime.h>
#include <cuda_bf16.h>
#include <cstdint>
#include <math.h>

#define B_    16
#define N_    4096
#define CIN   256
#define CH_   256
#define DW    512
#define IN_   128

// tcgen05 asm only compiles under an 'a'-suffixed target pass.
#if defined(__CUDA_ARCH_FEAT_SM103_ALL) || defined(__CUDA_ARCH_FEAT_SM100_ALL) || defined(__CUDA_ARCH_FEAT_SM101_ALL)
#define USE_TCGEN05 1
#else
#define USE_TCGEN05 0
#endif

// -------------------- device scratch --------------------
__device__ float g_attw[B_ * DW];
// 8 pre-swizzled W tile images, each exactly the 64KB SMEM image (SW128 baked in):
// tile t = (kb, hi/lo): t=2*kb -> whi(kb), t=2*kb+1 -> wlo(kb). [8][512 rows][128 B]
__device__ __nv_bfloat16 g_w3[8 * 512 * 64];

// -------------------- PTX helpers --------------------
__device__ __forceinline__ uint32_t smem_u32(const void* p) {
    uint32_t a;
    asm("{ .reg .u64 t; cvta.to.shared.u64 t, %1; cvt.u32.u64 %0, t; }" : "=r"(a) : "l"(p));
    return a;
}
__device__ __forceinline__ uint32_t elect_one() {
    uint32_t pred;
    asm volatile("{\n\t.reg .pred p;\n\telect.sync _|p, 0xFFFFFFFF;\n\tselp.b32 %0, 1, 0, p;\n\t}" : "=r"(pred));
    return pred;
}
#define TCGEN05_ALLOC(sa, n) \
    asm volatile("tcgen05.alloc.cta_group::1.sync.aligned.shared::cta.b32 [%0], %1;" :: "r"((uint32_t)(sa)), "r"((uint32_t)(n)) : "memory")
#define TCGEN05_DEALLOC(t, n) \
    asm volatile("tcgen05.dealloc.cta_group::1.sync.aligned.b32 %0, %1;" :: "r"(t), "r"((uint32_t)(n)))
#define TCGEN05_RELINQ() \
    asm volatile("tcgen05.relinquish_alloc_permit.cta_group::1.sync.aligned;")
#define TCGEN05_COMMIT(mb) \
    asm volatile("tcgen05.commit.cta_group::1.mbarrier::arrive::one.shared::cluster.b64 [%0];" :: "r"((uint32_t)(mb)) : "memory")
#define TCGEN05_WAIT_LD() asm volatile("tcgen05.wait::ld.sync.aligned;" ::: "memory")
#define TCGEN05_FENCE_AFTER() asm volatile("tcgen05.fence::after_thread_sync;" ::: "memory")
#define MBARRIER_INIT(mb, cnt) \
    asm volatile("mbarrier.init.shared.b64 [%0], %1;" :: "r"((uint32_t)(mb)), "r"((uint32_t)(cnt)) : "memory")
#define MBARRIER_ARRIVE(mb) \
    asm volatile("mbarrier.arrive.shared.b64 _, [%0];" :: "r"((uint32_t)(mb)) : "memory")
#define MBARRIER_EXPECT_TX(mb, bytes) \
    asm volatile("mbarrier.arrive.expect_tx.shared.b64 _, [%0], %1;" :: "r"((uint32_t)(mb)), "r"((uint32_t)(bytes)) : "memory")
#define MBARRIER_WAIT_PARITY(mb, ph) do { \
    uint32_t _m = (uint32_t)(mb), _p = (uint32_t)(ph), _d; \
    asm volatile("{\n\t.reg .pred p;\n\tmbarrier.try_wait.parity.acquire.cta.shared::cta.b64 p, [%1], %2;\n\tselp.b32 %0, 1, 0, p;\n\t}" \
        : "=r"(_d) : "r"(_m), "r"(_p) : "memory"); \
    if (!_d) { \
        asm volatile("{\n\t.reg .pred P1;\n\tWL_%=:\n\tmbarrier.try_wait.parity.acquire.cta.shared::cta.b64 P1, [%0], %1, 0x989680;\n\t@P1 bra.uni WD_%=;\n\tbra.uni WL_%=;\n\tWD_%=:\n\t}" \
            :: "r"(_m), "r"(_p) : "memory"); \
    } \
} while (0)
#define BULK_G2S(dst, src, bytes, mb) \
    asm volatile("cp.async.bulk.shared::cta.global.mbarrier::complete_tx::bytes [%0], [%1], %2, [%3];" \
        :: "r"((uint32_t)(dst)), "l"(src), "r"((uint32_t)(bytes)), "r"((uint32_t)(mb)) : "memory")
#define TCGEN05_LD_X32(r, ta) \
    asm volatile("tcgen05.ld.sync.aligned.32x32b.x32.b32 " \
        "{%0,%1,%2,%3,%4,%5,%6,%7,%8,%9,%10,%11,%12,%13,%14,%15," \
        "%16,%17,%18,%19,%20,%21,%22,%23,%24,%25,%26,%27,%28,%29,%30,%31}, [%32];" \
        : "=r"((r)[0]),"=r"((r)[1]),"=r"((r)[2]),"=r"((r)[3]),"=r"((r)[4]),"=r"((r)[5]),"=r"((r)[6]),"=r"((r)[7]), \
          "=r"((r)[8]),"=r"((r)[9]),"=r"((r)[10]),"=r"((r)[11]),"=r"((r)[12]),"=r"((r)[13]),"=r"((r)[14]),"=r"((r)[15]), \
          "=r"((r)[16]),"=r"((r)[17]),"=r"((r)[18]),"=r"((r)[19]),"=r"((r)[20]),"=r"((r)[21]),"=r"((r)[22]),"=r"((r)[23]), \
          "=r"((r)[24]),"=r"((r)[25]),"=r"((r)[26]),"=r"((r)[27]),"=r"((r)[28]),"=r"((r)[29]),"=r"((r)[30]),"=r"((r)[31]) \
        : "r"(ta))

static constexpr uint64_t SMEM_DESC_BASE_SW128 =
    (uint64_t(2) << 61) | (uint64_t(1) << 46) | (uint64_t(64) << 32) | (uint64_t(1) << 16);
#define MAKE_SMEM_DESC(a) (SMEM_DESC_BASE_SW128 | ((uint64_t)((a) >> 4) & 0x3FFF))

#if USE_TCGEN05
// SS-mode cg1 bf16 MMA: D[128,256] += A[128,16] * B[256,16]^T
__device__ __forceinline__ void mma_f16_ss(uint32_t d, uint64_t ad, uint64_t bd, uint32_t idesc, bool acc) {
    uint32_t en = acc ? 1u : 0u;
    asm volatile(
        "{\n\t.reg .pred p;\n\tsetp.ne.u32 p, %5, 0;\n\t"
        "tcgen05.mma.cta_group::1.kind::f16 [%0], %1, %2, %3, {%4, %4, %4, %4}, p;\n\t}"
        :: "r"(d), "l"(ad), "l"(bd), "r"(idesc), "r"(0u), "r"(en) : "memory");
}
#endif
// idesc: F32 accum, BF16 x BF16, M=128, N=256
static constexpr uint32_t IDESC =
    (1u << 4) | (1u << 7) | (1u << 10) | ((256u / 8u) << 17) | ((128u / 16u) << 24);

// fp32 -> bf16 hi/lo split, packed pairs
__device__ __forceinline__ void split4(const float4 v, uint32_t& h01, uint32_t& h23,
                                       uint32_t& l01, uint32_t& l23) {
    __nv_bfloat162 h0 = __floats2bfloat162_rn(v.x, v.y);
    __nv_bfloat162 h1 = __floats2bfloat162_rn(v.z, v.w);
    __nv_bfloat162 l0 = __floats2bfloat162_rn(v.x - __bfloat162float(h0.x),
                                              v.y - __bfloat162float(h0.y));
    __nv_bfloat162 l1 = __floats2bfloat162_rn(v.z - __bfloat162float(h1.x),
                                              v.w - __bfloat162float(h1.y));
    h01 = *(uint32_t*)&h0; h23 = *(uint32_t*)&h1;
    l01 = *(uint32_t*)&l0; l23 = *(uint32_t*)&l1;
}

// ---------------------------------------------------------------------------
// Kernel 1 (fused setup): blocks 0..15 attention path, blocks 16..143 prep_w.
// Attention: only rows n=0 / n=1024 per batch survive the rSoftMax slice;
// b_fc2 cancels in the pair difference.
// prep_w: writes g_w3 as 8 SW128-pre-swizzled 64KB tile images.
// ---------------------------------------------------------------------------
__global__ __launch_bounds__(256) void setup_kernel(
    const float* __restrict__ x,
    const float* __restrict__ w_conv,
    const float* __restrict__ b_conv,
    const float* __restrict__ w_fc1,
    const float* __restrict__ b_fc1,
    const float* __restrict__ w_fc2)
{
    const int tid = threadIdx.x;

    if (blockIdx.x >= 16) {
        // ---- prep_w ----
        const int gi = ((blockIdx.x - 16) * 256 + tid) * 4;   // fp32 flat idx in [512][256]
        float4 v = *(const float4*)(w_conv + gi);
        const int d = gi >> 8, k = gi & 255;
        uint32_t h01, h23, l01, l23;
        split4(v, h01, h23, l01, l23);
        const int kb = k >> 6;
        const uint32_t c  = (uint32_t)(k & 63) * 2;            // byte col in 128B row
        const uint32_t sw = c ^ ((uint32_t)(d & 7) << 4);
        char* basehi = (char*)g_w3 + (size_t)(2 * kb) * 65536 + (size_t)d * 128 + sw;
        *(uint2*)basehi           = make_uint2(h01, h23);
        *(uint2*)(basehi + 65536) = make_uint2(l01, l23);
        return;
    }

    // ---- attention ----
    const int b = blockIdx.x;
    __shared__ float xs0[CIN], xs1[CIN];
    __shared__ float h0[DW], h1[DW];
    __shared__ float gap0[CH_], gap1[CH_];
    __shared__ float g0[IN_], g1[IN_], gd[IN_];

    xs0[tid] = x[(b * N_ + 0)    * CIN + tid];
    xs1[tid] = x[(b * N_ + 1024) * CIN + tid];
    __syncthreads();

    #pragma unroll
    for (int dd = 0; dd < 2; dd++) {
        const int d = tid + dd * 256;
        const float4* w = (const float4*)(w_conv + d * CIN);
        float s0 = 0.f, s1 = 0.f;
        #pragma unroll 8
        for (int k4 = 0; k4 < CIN / 4; k4++) {
            float4 wv = w[k4];
            float4 x0 = ((const float4*)xs0)[k4];
            float4 x1 = ((const float4*)xs1)[k4];
            s0 += wv.x * x0.x + wv.y * x0.y + wv.z * x0.z + wv.w * x0.w;
            s1 += wv.x * x1.x + wv.y * x1.y + wv.z * x1.z + wv.w * x1.w;
        }
        const float bb = b_conv[d];
        h0[d] = fmaxf(s0 + bb, 0.f);
        h1[d] = fmaxf(s1 + bb, 0.f);
    }
    __syncthreads();

    gap0[tid] = h0[tid] + h0[tid + CH_];
    gap1[tid] = h1[tid] + h1[tid + CH_];
    __syncthreads();

    {
        const int i = tid & 127;
        const float* gp = (tid < 128) ? gap0 : gap1;
        const float4* w = (const float4*)(w_fc1 + i * CH_);
        float s = 0.f;
        #pragma unroll 8
        for (int k4 = 0; k4 < CH_ / 4; k4++) {
            float4 wv = w[k4];
            float4 gv = ((const float4*)gp)[k4];
            s += wv.x * gv.x + wv.y * gv.y + wv.z * gv.z + wv.w * gv.w;
        }
        s = fmaxf(s + b_fc1[i], 0.f);
        if (tid < 128) g0[i] = s; else g1[i] = s;
    }
    __syncthreads();
    if (tid < IN_) gd[tid] = g0[tid] - g1[tid];
    __syncthreads();

    #pragma unroll
    for (int dd = 0; dd < 2; dd++) {
        const int d = tid + dd * 256;
        const float4* w = (const float4*)(w_fc2 + d * IN_);
        float s = 0.f;
        #pragma unroll 8
        for (int k4 = 0; k4 < IN_ / 4; k4++) {
            float4 wv = w[k4];
            float4 gv = ((const float4*)gd)[k4];
            s += wv.x * gv.x + wv.y * gv.y + wv.z * gv.z + wv.w * gv.w;
        }
        g_attw[b * DW + d] = 1.f / (1.f + expf(-s));
    }
}

// ---------------------------------------------------------------------------
// Kernel 2: warp-specialized tcgen05 GEMM with fused x-split + epilogue.
// Per CTA: M=128 rows, N=512, K organized as 4 k-blocks of 64 fp32 cols.
// Per kb: products hi*whi, lo*whi, hi*wlo (whi tile reused twice).
// Warp 0 = MMA issue, warp 1 = W bulk-copy producer, warps 2-15 = A loaders.
// ---------------------------------------------------------------------------
#define A_OFF   1024
#define W_OFF   (1024 + 65536)
#define SMEM_TOTAL (1024 + 65536 + 131072)

__global__ __launch_bounds__(512, 1)
void gemm_kernel(const float* __restrict__ x,
                 const float* __restrict__ w_conv,
                 const float* __restrict__ b_conv,
                 float* __restrict__ out)
{
    extern __shared__ __align__(1024) char smem[];
    const int tid = threadIdx.x;
    const int m0  = blockIdx.x * 128;
    const int bb  = m0 >> 12;
    const int n0  = m0 & (N_ - 1);

#if USE_TCGEN05
    const uint32_t sb = smem_u32(smem);
    const int wid = tid >> 5, lid = tid & 31;

    const uint32_t WF0 = sb + 8,  WF1 = sb + 16;   // w_full
    const uint32_t WE0 = sb + 24, WE1 = sb + 32;   // w_empty
    const uint32_t AF0 = sb + 40, AF1 = sb + 48;   // a_full (count 448)
    const uint32_t AR0 = sb + 56, AR1 = sb + 64;   // a_free
    const uint32_t MDN = sb + 72;                  // all done

    if (wid == 0) TCGEN05_ALLOC(sb, 512);
    if (tid == 0) {
        MBARRIER_INIT(WF0, 1); MBARRIER_INIT(WF1, 1);
        MBARRIER_INIT(WE0, 1); MBARRIER_INIT(WE1, 1);
        MBARRIER_INIT(AF0, 448); MBARRIER_INIT(AF1, 448);
        MBARRIER_INIT(AR0, 1); MBARRIER_INIT(AR1, 1);
        MBARRIER_INIT(MDN, 1);
    }
    __syncthreads();
    uint32_t tmem;
    asm volatile("ld.shared.b32 %0, [%1];" : "=r"(tmem) : "r"(sb));

    if (wid == 0) {
        // ---------------- MMA warp ----------------
        if (elect_one()) {
            int wph0 = 0, wph1 = 0, afph[2] = {0, 0};
            for (int kb = 0; kb < 4; kb++) {
                const int q = kb & 1;
                MBARRIER_WAIT_PARITY(q ? AF1 : AF0, afph[q]); afph[q] ^= 1;
                const uint32_t ab = sb + A_OFF + q * 32768;
                const uint64_t ahi = MAKE_SMEM_DESC(ab);
                const uint64_t alo = MAKE_SMEM_DESC(ab + 16384);
                const uint64_t w0  = MAKE_SMEM_DESC(sb + W_OFF);
                const uint64_t w0b = MAKE_SMEM_DESC(sb + W_OFF + 32768);
                const uint64_t w1  = MAKE_SMEM_DESC(sb + W_OFF + 65536);
                const uint64_t w1b = MAKE_SMEM_DESC(sb + W_OFF + 65536 + 32768);

                MBARRIER_WAIT_PARITY(WF0, wph0); wph0 ^= 1;
                #pragma unroll
                for (int k = 0; k < 4; k++) {
                    const bool acc = !(kb == 0 && k == 0);
                    mma_f16_ss(tmem,       ahi + k * 2, w0  + k * 2, IDESC, acc);
                    mma_f16_ss(tmem + 256, ahi + k * 2, w0b + k * 2, IDESC, acc);
                }
                #pragma unroll
                for (int k = 0; k < 4; k++) {
                    mma_f16_ss(tmem,       alo + k * 2, w0  + k * 2, IDESC, true);
                    mma_f16_ss(tmem + 256, alo + k * 2, w0b + k * 2, IDESC, true);
                }
                TCGEN05_COMMIT(WE0);

                MBARRIER_WAIT_PARITY(WF1, wph1); wph1 ^= 1;
                #pragma unroll
                for (int k = 0; k < 4; k++) {
                    mma_f16_ss(tmem,       ahi + k * 2, w1  + k * 2, IDESC, true);
                    mma_f16_ss(tmem + 256, ahi + k * 2, w1b + k * 2, IDESC, true);
                }
                TCGEN05_COMMIT(WE1);
                TCGEN05_COMMIT(q ? AR1 : AR0);
            }
            TCGEN05_COMMIT(MDN);
        }
    } else if (wid == 1) {
        // ---------------- W producer ----------------
        if (elect_one()) {
            const char* wsrc = (const char*)g_w3;
            int eph[2] = {0, 0};
            for (int t = 0; t < 8; t++) {
                const int bf = t & 1;
                if (t >= 2) { MBARRIER_WAIT_PARITY(bf ? WE1 : WE0, eph[bf]); eph[bf] ^= 1; }
                const uint32_t mb = bf ? WF1 : WF0;
                MBARRIER_EXPECT_TX(mb, 65536);
                BULK_G2S(sb + W_OFF + bf * 65536, wsrc + (size_t)t * 65536, 65536, mb);
            }
        }
    } else {
        // ---------------- A loaders (448 threads) ----------------
        const int lt = tid - 64;
        int frph[2] = {0, 0};
        for (int kb = 0; kb < 4; kb++) {
            const int q = kb & 1;
            if (kb >= 2) { MBARRIER_WAIT_PARITY(q ? AR1 : AR0, frph[q]); frph[q] ^= 1; }
            const uint32_t ab = sb + A_OFF + q * 32768;
            for (int f = lt; f < 2048; f += 448) {
                const int r = f >> 4, qq = f & 15;
                const float4 v = *(const float4*)&x[(size_t)(m0 + r) * 256 + kb * 64 + qq * 4];
                uint32_t h01, h23, l01, l23;
                split4(v, h01, h23, l01, l23);
                const uint32_t off = (uint32_t)r * 128 + (((uint32_t)qq * 8) ^ ((uint32_t)(r & 7) << 4));
                asm volatile("st.shared.v2.b32 [%0], {%1,%2};" :: "r"(ab + off), "r"(h01), "r"(h23) : "memory");
                asm volatile("st.shared.v2.b32 [%0], {%1,%2};" :: "r"(ab + 16384 + off), "r"(l01), "r"(l23) : "memory");
            }
            asm volatile("fence.proxy.async.shared::cta;" ::: "memory");
            MBARRIER_ARRIVE(q ? AF1 : AF0);
        }
    }

    // ---------------- epilogue ----------------
    MBARRIER_WAIT_PARITY(MDN, 0);
    TCGEN05_FENCE_AFTER();

    if (tid < 128) {
        const int m = wid * 32 + lid;
        const int n = n0 + m;
        float* __restrict__ orow = out + ((size_t)n * B_ + bb) * CH_;
        const float* __restrict__ aw = g_attw + bb * DW;
        #pragma unroll 1
        for (int cc = 0; cc < 8; cc++) {
            uint32_t hr0[32], hr1[32];
            TCGEN05_LD_X32(hr0, tmem + cc * 32);
            TCGEN05_LD_X32(hr1, tmem + 256 + cc * 32);
            TCGEN05_WAIT_LD();
            #pragma unroll
            for (int q = 0; q < 8; q++) {
                const int ci = cc * 32 + q * 4;
                float4 b0 = *(const float4*)&b_conv[ci];
                float4 b1 = *(const float4*)&b_conv[256 + ci];
                float4 a0 = *(const float4*)&aw[ci];
                float4 a1 = *(const float4*)&aw[256 + ci];
                float4 o;
                o.x = a0.x * fmaxf(__uint_as_float(hr0[q*4+0]) + b0.x, 0.f)
                    + a1.x * fmaxf(__uint_as_float(hr1[q*4+0]) + b1.x, 0.f);
                o.y = a0.y * fmaxf(__uint_as_float(hr0[q*4+1]) + b0.y, 0.f)
                    + a1.y * fmaxf(__uint_as_float(hr1[q*4+1]) + b1.y, 0.f);
                o.z = a0.z * fmaxf(__uint_as_float(hr0[q*4+2]) + b0.z, 0.f)
                    + a1.z * fmaxf(__uint_as_float(hr1[q*4+2]) + b1.z, 0.f);
                o.w = a0.w * fmaxf(__uint_as_float(hr0[q*4+3]) + b0.w, 0.f)
                    + a1.w * fmaxf(__uint_as_float(hr1[q*4+3]) + b1.w, 0.f);
                *(float4*)(orow + ci) = o;
            }
        }
    }
    __syncthreads();
    if (wid == 0) { TCGEN05_DEALLOC(tmem, 512); TCGEN05_RELINQ(); }

#else  // ------------------- fp32 FFMA fallback (plain sm_103) --------------
    float (*As)[64]  = (float(*)[64])smem;
    float (*Bs)[516] = (float(*)[516])(smem + 16 * 64 * 4);

    const int trow = tid >> 6;
    const int tcol = tid & 63;
    const int aM = tid >> 2, aK = (tid & 3) << 2;
    const int bD = tid >> 2, bK = (tid & 3) << 2;

    for (int sub = 0; sub < 2; sub++) {
        const int ms = m0 + sub * 64;
        float acc[8][8];
        #pragma unroll
        for (int i = 0; i < 8; i++)
            #pragma unroll
            for (int jj = 0; jj < 8; jj++) acc[i][jj] = 0.f;

        float4 aReg = make_float4(0.f, 0.f, 0.f, 0.f);
        float4 bReg[4];
        if (tid < 256)
            aReg = *(const float4*)&x[(size_t)(ms + aM) * CIN + aK];
        #pragma unroll
        for (int p = 0; p < 4; p++)
            bReg[p] = *(const float4*)&w_conv[(size_t)(bD + p * 128) * CIN + bK];

        for (int ks = 0; ks < CIN; ks += 16) {
            __syncthreads();
            if (tid < 256) {
                As[aK + 0][aM] = aReg.x; As[aK + 1][aM] = aReg.y;
                As[aK + 2][aM] = aReg.z; As[aK + 3][aM] = aReg.w;
            }
            #pragma unroll
            for (int p = 0; p < 4; p++) {
                const int d = bD + p * 128;
                Bs[bK + 0][d] = bReg[p].x; Bs[bK + 1][d] = bReg[p].y;
                Bs[bK + 2][d] = bReg[p].z; Bs[bK + 3][d] = bReg[p].w;
            }
            __syncthreads();
            if (ks + 16 < CIN) {
                const int kn = ks + 16;
                if (tid < 256)
                    aReg = *(const float4*)&x[(size_t)(ms + aM) * CIN + kn + aK];
                #pragma unroll
                for (int p = 0; p < 4; p++)
                    bReg[p] = *(const float4*)&w_conv[(size_t)(bD + p * 128) * CIN + kn + bK];
            }
            #pragma unroll
            for (int k = 0; k < 16; k++) {
                float a[8], bf[8];
                *(float4*)&a[0]  = *(const float4*)&As[k][trow * 8];
                *(float4*)&a[4]  = *(const float4*)&As[k][trow * 8 + 4];
                *(float4*)&bf[0] = *(const float4*)&Bs[k][tcol * 4];
                *(float4*)&bf[4] = *(const float4*)&Bs[k][tcol * 4 + 256];
                #pragma unroll
                for (int i = 0; i < 8; i++)
                    #pragma unroll
                    for (int jj = 0; jj < 8; jj++)
                        acc[i][jj] += a[i] * bf[jj];
            }
        }
        __syncthreads();

        const int cbase = tcol * 4;
        float a0[4], a1[4], bias0[4], bias1[4];
        #pragma unroll
        for (int jj = 0; jj < 4; jj++) {
            a0[jj]    = g_attw[bb * DW + cbase + jj];
            a1[jj]    = g_attw[bb * DW + 256 + cbase + jj];
            bias0[jj] = b_conv[cbase + jj];
            bias1[jj] = b_conv[256 + cbase + jj];
        }
        #pragma unroll
        for (int i = 0; i < 8; i++) {
            const int n = n0 + sub * 64 + trow * 8 + i;
            float4 o;
            o.x = a0[0] * fmaxf(acc[i][0] + bias0[0], 0.f) + a1[0] * fmaxf(acc[i][4] + bias1[0], 0.f);
            o.y = a0[1] * fmaxf(acc[i][1] + bias0[1], 0.f) + a1[1] * fmaxf(acc[i][5] + bias1[1], 0.f);
            o.z = a0[2] * fmaxf(acc[i][2] + bias0[2], 0.f) + a1[2] * fmaxf(acc[i][6] + bias1[2], 0.f);
            o.w = a0[3] * fmaxf(acc[i][3] + bias0[3], 0.f) + a1[3] * fmaxf(acc[i][7] + bias1[3], 0.f);
            *(float4*)&out[((size_t)n * B_ + bb) * CH_ + cbase] = o;
        }
    }
#endif
}

extern "C" void kernel_launch(void* const* d_in, const int* in_sizes, int n_in,
                              void* d_out, int out_size) {
    const float* x      = (const float*)d_in[0];
    const float* w_conv = (const float*)d_in[1];
    const float* b_conv = (const float*)d_in[2];
    const float* w_fc1  = (const float*)d_in[3];
    const float* b_fc1  = (const float*)d_in[4];
    const float* w_fc2  = (const float*)d_in[5];
    // d_in[6] = b_fc2: cancels in the softmax-pair difference, unused.
    float* out = (float*)d_out;

    cudaFuncSetAttribute(gemm_kernel, cudaFuncAttributeMaxDynamicSharedMemorySize, SMEM_TOTAL);

    setup_kernel<<<16 + 128, 256>>>(x, w_conv, b_conv, w_fc1, b_fc1, w_fc2);
    gemm_kernel<<<(B_ * N_) / 128, 512, SMEM_TOTAL>>>(x, w_conv, b_conv, out);
}

// round 5
// speedup vs baseline: 2.9768x; 1.0762x over previous
#include <cuda_runtime.h>
#include <cuda_bf16.h>
#include <cstdint>
#include <math.h>

#define B_    16
#define N_    4096
#define CIN   256
#define CH_   256
#define DW    512
#define IN_   128

// tcgen05 asm only compiles under an 'a'-suffixed target pass.
#if defined(__CUDA_ARCH_FEAT_SM103_ALL) || defined(__CUDA_ARCH_FEAT_SM100_ALL) || defined(__CUDA_ARCH_FEAT_SM101_ALL)
#define USE_TCGEN05 1
#else
#define USE_TCGEN05 0
#endif

// -------------------- device scratch --------------------
__device__ float g_attw[B_ * DW];
__device__ float g_h[B_ * 2 * DW];   // conv rows n=0 / n=1024 per batch
// 16 pre-swizzled W chunk images of 32KB each (256 rows x 128B, SW128 baked in).
// chunk t = kb*4 + part, part: 0=(hi,nh0) 1=(hi,nh1) 2=(lo,nh0) 3=(lo,nh1).
// Row permutation: w_conv row d (c=d&255, r=d>>8) -> nh=c>>7, local row=(c&127)+r*128.
__device__ __nv_bfloat16 g_w3[16 * 256 * 64];

// -------------------- PTX helpers --------------------
__device__ __forceinline__ uint32_t smem_u32(const void* p) {
    uint32_t a;
    asm("{ .reg .u64 t; cvta.to.shared.u64 t, %1; cvt.u32.u64 %0, t; }" : "=r"(a) : "l"(p));
    return a;
}
__device__ __forceinline__ uint32_t elect_one() {
    uint32_t pred;
    asm volatile("{\n\t.reg .pred p;\n\telect.sync _|p, 0xFFFFFFFF;\n\tselp.b32 %0, 1, 0, p;\n\t}" : "=r"(pred));
    return pred;
}
#define TCGEN05_ALLOC(sa, n) \
    asm volatile("tcgen05.alloc.cta_group::1.sync.aligned.shared::cta.b32 [%0], %1;" :: "r"((uint32_t)(sa)), "r"((uint32_t)(n)) : "memory")
#define TCGEN05_DEALLOC(t, n) \
    asm volatile("tcgen05.dealloc.cta_group::1.sync.aligned.b32 %0, %1;" :: "r"(t), "r"((uint32_t)(n)))
#define TCGEN05_RELINQ() \
    asm volatile("tcgen05.relinquish_alloc_permit.cta_group::1.sync.aligned;")
#define TCGEN05_COMMIT(mb) \
    asm volatile("tcgen05.commit.cta_group::1.mbarrier::arrive::one.shared::cluster.b64 [%0];" :: "r"((uint32_t)(mb)) : "memory")
#define TCGEN05_WAIT_LD() asm volatile("tcgen05.wait::ld.sync.aligned;" ::: "memory")
#define TCGEN05_FENCE_AFTER() asm volatile("tcgen05.fence::after_thread_sync;" ::: "memory")
#define MBARRIER_INIT(mb, cnt) \
    asm volatile("mbarrier.init.shared.b64 [%0], %1;" :: "r"((uint32_t)(mb)), "r"((uint32_t)(cnt)) : "memory")
#define MBARRIER_ARRIVE(mb) \
    asm volatile("mbarrier.arrive.shared.b64 _, [%0];" :: "r"((uint32_t)(mb)) : "memory")
#define MBARRIER_EXPECT_TX(mb, bytes) \
    asm volatile("mbarrier.arrive.expect_tx.shared.b64 _, [%0], %1;" :: "r"((uint32_t)(mb)), "r"((uint32_t)(bytes)) : "memory")
#define MBARRIER_WAIT_PARITY(mb, ph) do { \
    uint32_t _m = (uint32_t)(mb), _p = (uint32_t)(ph), _d; \
    asm volatile("{\n\t.reg .pred p;\n\tmbarrier.try_wait.parity.acquire.cta.shared::cta.b64 p, [%1], %2;\n\tselp.b32 %0, 1, 0, p;\n\t}" \
        : "=r"(_d) : "r"(_m), "r"(_p) : "memory"); \
    if (!_d) { \
        asm volatile("{\n\t.reg .pred P1;\n\tWL_%=:\n\tmbarrier.try_wait.parity.acquire.cta.shared::cta.b64 P1, [%0], %1, 0x989680;\n\t@P1 bra.uni WD_%=;\n\tbra.uni WL_%=;\n\tWD_%=:\n\t}" \
            :: "r"(_m), "r"(_p) : "memory"); \
    } \
} while (0)
#define BULK_G2S(dst, src, bytes, mb) \
    asm volatile("cp.async.bulk.shared::cta.global.mbarrier::complete_tx::bytes [%0], [%1], %2, [%3];" \
        :: "r"((uint32_t)(dst)), "l"(src), "r"((uint32_t)(bytes)), "r"((uint32_t)(mb)) : "memory")
#define TCGEN05_LD_X32(r, ta) \
    asm volatile("tcgen05.ld.sync.aligned.32x32b.x32.b32 " \
        "{%0,%1,%2,%3,%4,%5,%6,%7,%8,%9,%10,%11,%12,%13,%14,%15," \
        "%16,%17,%18,%19,%20,%21,%22,%23,%24,%25,%26,%27,%28,%29,%30,%31}, [%32];" \
        : "=r"((r)[0]),"=r"((r)[1]),"=r"((r)[2]),"=r"((r)[3]),"=r"((r)[4]),"=r"((r)[5]),"=r"((r)[6]),"=r"((r)[7]), \
          "=r"((r)[8]),"=r"((r)[9]),"=r"((r)[10]),"=r"((r)[11]),"=r"((r)[12]),"=r"((r)[13]),"=r"((r)[14]),"=r"((r)[15]), \
          "=r"((r)[16]),"=r"((r)[17]),"=r"((r)[18]),"=r"((r)[19]),"=r"((r)[20]),"=r"((r)[21]),"=r"((r)[22]),"=r"((r)[23]), \
          "=r"((r)[24]),"=r"((r)[25]),"=r"((r)[26]),"=r"((r)[27]),"=r"((r)[28]),"=r"((r)[29]),"=r"((r)[30]),"=r"((r)[31]) \
        : "r"(ta))

static constexpr uint64_t SMEM_DESC_BASE_SW128 =
    (uint64_t(2) << 61) | (uint64_t(1) << 46) | (uint64_t(64) << 32) | (uint64_t(1) << 16);
#define MAKE_SMEM_DESC(a) (SMEM_DESC_BASE_SW128 | ((uint64_t)((a) >> 4) & 0x3FFF))

#if USE_TCGEN05
// SS-mode cg1 bf16 MMA: D[128,256] += A[128,16] * B[256,16]^T
__device__ __forceinline__ void mma_f16_ss(uint32_t d, uint64_t ad, uint64_t bd, uint32_t idesc, bool acc) {
    uint32_t en = acc ? 1u : 0u;
    asm volatile(
        "{\n\t.reg .pred p;\n\tsetp.ne.u32 p, %5, 0;\n\t"
        "tcgen05.mma.cta_group::1.kind::f16 [%0], %1, %2, %3, {%4, %4, %4, %4}, p;\n\t}"
        :: "r"(d), "l"(ad), "l"(bd), "r"(idesc), "r"(0u), "r"(en) : "memory");
}
#endif
// idesc: F32 accum, BF16 x BF16, M=128, N=256
static constexpr uint32_t IDESC =
    (1u << 4) | (1u << 7) | (1u << 10) | ((256u / 8u) << 17) | ((128u / 16u) << 24);

// fp32 -> bf16 hi/lo split, packed pairs
__device__ __forceinline__ void split4(const float4 v, uint32_t& h01, uint32_t& h23,
                                       uint32_t& l01, uint32_t& l23) {
    __nv_bfloat162 h0 = __floats2bfloat162_rn(v.x, v.y);
    __nv_bfloat162 h1 = __floats2bfloat162_rn(v.z, v.w);
    __nv_bfloat162 l0 = __floats2bfloat162_rn(v.x - __bfloat162float(h0.x),
                                              v.y - __bfloat162float(h0.y));
    __nv_bfloat162 l1 = __floats2bfloat162_rn(v.z - __bfloat162float(h1.x),
                                              v.w - __bfloat162float(h1.y));
    h01 = *(uint32_t*)&h0; h23 = *(uint32_t*)&h1;
    l01 = *(uint32_t*)&l0; l23 = *(uint32_t*)&l1;
}

// ---------------------------------------------------------------------------
// Setup 1: blocks 0..31 = conv rows (batch = blk>>1, n = (blk&1)*1024) -> g_h.
//          blocks 32..95 = prep_w (permuted + SW128-pre-swizzled chunk images).
// ---------------------------------------------------------------------------
__global__ __launch_bounds__(512) void setup1_kernel(
    const float* __restrict__ x,
    const float* __restrict__ w_conv,
    const float* __restrict__ b_conv)
{
    const int tid = threadIdx.x;

    if (blockIdx.x >= 32) {
        // ---- prep_w: 64 blocks x 512 threads x 4 floats = 131072 elements ----
        const int gi = ((blockIdx.x - 32) * 512 + tid) * 4;
        float4 v = *(const float4*)(w_conv + gi);
        const int d = gi >> 8, k = gi & 255;
        uint32_t h01, h23, l01, l23;
        split4(v, h01, h23, l01, l23);
        const int c = d & 255, r = d >> 8;
        const int nh = c >> 7;
        const int lrow = (c & 127) + (r << 7);
        const int kb = k >> 6, kc = k & 63;
        const uint32_t off = (uint32_t)lrow * 128 + (((uint32_t)kc * 2) ^ ((uint32_t)(lrow & 7) << 4));
        char* basehi = (char*)g_w3 + (size_t)(kb * 4 + nh) * 32768 + off;        // hi chunk
        char* baselo = (char*)g_w3 + (size_t)(kb * 4 + 2 + nh) * 32768 + off;    // lo chunk
        *(uint2*)basehi = make_uint2(h01, h23);
        *(uint2*)baselo = make_uint2(l01, l23);
        return;
    }

    // ---- conv row: 512 dots of length 256 ----
    const int b   = blockIdx.x >> 1;
    const int row = (blockIdx.x & 1) * 1024;
    __shared__ float xs[CIN];
    if (tid < CIN) xs[tid] = x[((size_t)b * N_ + row) * CIN + tid];
    __syncthreads();

    const int d = tid;
    const float4* w = (const float4*)(w_conv + d * CIN);
    float s = 0.f;
    #pragma unroll 8
    for (int k4 = 0; k4 < CIN / 4; k4++) {
        float4 wv = w[k4];
        float4 xv = ((const float4*)xs)[k4];
        s += wv.x * xv.x + wv.y * xv.y + wv.z * xv.z + wv.w * xv.w;
    }
    g_h[(b * 2 + (blockIdx.x & 1)) * DW + d] = fmaxf(s + b_conv[d], 0.f);
}

// ---------------------------------------------------------------------------
// Setup 2: fc chain per batch. Only rows n=0 / n=1024 survive the rSoftMax
// slice; b_fc2 cancels in the pair difference. attw = sigmoid(delta).
// ---------------------------------------------------------------------------
__global__ __launch_bounds__(256) void setup2_kernel(
    const float* __restrict__ w_fc1,
    const float* __restrict__ b_fc1,
    const float* __restrict__ w_fc2)
{
    const int b   = blockIdx.x;
    const int tid = threadIdx.x;
    __shared__ float gap0[CH_], gap1[CH_];
    __shared__ float g0[IN_], g1[IN_], gd[IN_];

    const float* h0 = g_h + (b * 2 + 0) * DW;
    const float* h1 = g_h + (b * 2 + 1) * DW;
    gap0[tid] = h0[tid] + h0[tid + CH_];
    gap1[tid] = h1[tid] + h1[tid + CH_];
    __syncthreads();

    {
        const int i = tid & 127;
        const float* gp = (tid < 128) ? gap0 : gap1;
        const float4* w = (const float4*)(w_fc1 + i * CH_);
        float s = 0.f;
        #pragma unroll 8
        for (int k4 = 0; k4 < CH_ / 4; k4++) {
            float4 wv = w[k4];
            float4 gv = ((const float4*)gp)[k4];
            s += wv.x * gv.x + wv.y * gv.y + wv.z * gv.z + wv.w * gv.w;
        }
        s = fmaxf(s + b_fc1[i], 0.f);
        if (tid < 128) g0[i] = s; else g1[i] = s;
    }
    __syncthreads();
    if (tid < IN_) gd[tid] = g0[tid] - g1[tid];
    __syncthreads();

    #pragma unroll
    for (int dd = 0; dd < 2; dd++) {
        const int d = tid + dd * 256;
        const float4* w = (const float4*)(w_fc2 + d * IN_);
        float s = 0.f;
        #pragma unroll 8
        for (int k4 = 0; k4 < IN_ / 4; k4++) {
            float4 wv = w[k4];
            float4 gv = ((const float4*)gd)[k4];
            s += wv.x * gv.x + wv.y * gv.y + wv.z * gv.z + wv.w * gv.w;
        }
        g_attw[b * DW + d] = 1.f / (1.f + expf(-s));
    }
}

// ---------------------------------------------------------------------------
// GEMM: warp-specialized tcgen05, M=128, N=512, K=3x256 bf16 products.
// W streamed as 16 x 32KB chunks through a 4-stage mbarrier ring (bulk copy).
// Warp 0 = MMA issue, warp 1 = W producer, warps 2-15 = A loaders (LDG+split).
// Epilogue on 8 warps (col-split), bias+ReLU+sigmoid radix combine, [N,B,CH].
// ---------------------------------------------------------------------------
#define A_OFF   1024
#define W_OFF   (1024 + 65536)
#define SMEM_TOTAL (1024 + 65536 + 4 * 32768)

__global__ __launch_bounds__(512, 1)
void gemm_kernel(const float* __restrict__ x,
                 const float* __restrict__ w_conv,
                 const float* __restrict__ b_conv,
                 float* __restrict__ out)
{
    extern __shared__ __align__(1024) char smem[];
    const int tid = threadIdx.x;
    const int m0  = blockIdx.x * 128;
    const int bb  = m0 >> 12;
    const int n0  = m0 & (N_ - 1);

#if USE_TCGEN05
    const uint32_t sb = smem_u32(smem);
    const int wid = tid >> 5, lid = tid & 31;

    // mbarriers: WF[4] @8, WE[4] @40, AF[2] @72, AR[2] @88, MDN @104
    #define WF(s) (sb + 8  + (s) * 8)
    #define WE(s) (sb + 40 + (s) * 8)
    #define AF(q) (sb + 72 + (q) * 8)
    #define AR(q) (sb + 88 + (q) * 8)
    const uint32_t MDN = sb + 104;

    if (wid == 0) TCGEN05_ALLOC(sb, 512);
    if (tid == 0) {
        #pragma unroll
        for (int s = 0; s < 4; s++) { MBARRIER_INIT(WF(s), 1); MBARRIER_INIT(WE(s), 1); }
        MBARRIER_INIT(AF(0), 448); MBARRIER_INIT(AF(1), 448);
        MBARRIER_INIT(AR(0), 1);   MBARRIER_INIT(AR(1), 1);
        MBARRIER_INIT(MDN, 1);
    }
    __syncthreads();
    uint32_t tmem;
    asm volatile("ld.shared.b32 %0, [%1];" : "=r"(tmem) : "r"(sb));

    if (wid == 0) {
        // ---------------- MMA warp ----------------
        if (elect_one()) {
            int afph[2] = {0, 0};
            for (int kb = 0; kb < 4; kb++) {
                const int q = kb & 1;
                MBARRIER_WAIT_PARITY(AF(q), afph[q]); afph[q] ^= 1;
                const uint32_t ab = sb + A_OFF + q * 32768;
                const uint64_t ahi = MAKE_SMEM_DESC(ab);
                const uint64_t alo = MAKE_SMEM_DESC(ab + 16384);
                #pragma unroll
                for (int part = 0; part < 4; part++) {
                    const int nh = part & 1, islo = part >> 1;
                    MBARRIER_WAIT_PARITY(WF(part), kb & 1);
                    const uint64_t wd = MAKE_SMEM_DESC(sb + W_OFF + part * 32768);
                    const uint32_t dst = tmem + nh * 256;
                    #pragma unroll
                    for (int k = 0; k < 4; k++)
                        mma_f16_ss(dst, ahi + k * 2, wd + k * 2, IDESC,
                                   !(kb == 0 && islo == 0 && k == 0));
                    if (!islo) {
                        #pragma unroll
                        for (int k = 0; k < 4; k++)
                            mma_f16_ss(dst, alo + k * 2, wd + k * 2, IDESC, true);
                    }
                    TCGEN05_COMMIT(WE(part));
                }
                TCGEN05_COMMIT(AR(q));
            }
            TCGEN05_COMMIT(MDN);
        }
    } else if (wid == 1) {
        // ---------------- W producer: 16 x 32KB chunks, 4-stage ring ----------
        if (elect_one()) {
            const char* wsrc = (const char*)g_w3;
            for (int t = 0; t < 16; t++) {
                const int s = t & 3, kb = t >> 2;
                if (t >= 4) MBARRIER_WAIT_PARITY(WE(s), (kb - 1) & 1);
                MBARRIER_EXPECT_TX(WF(s), 32768);
                BULK_G2S(sb + W_OFF + s * 32768, wsrc + (size_t)t * 32768, 32768, WF(s));
            }
        }
    } else {
        // ---------------- A loaders (448 threads) ----------------
        const int lt = tid - 64;
        int frph[2] = {0, 0};
        for (int kb = 0; kb < 4; kb++) {
            const int q = kb & 1;
            if (kb >= 2) { MBARRIER_WAIT_PARITY(AR(q), frph[q]); frph[q] ^= 1; }
            const uint32_t ab = sb + A_OFF + q * 32768;
            for (int f = lt; f < 2048; f += 448) {
                const int r = f >> 4, qq = f & 15;
                const float4 v = *(const float4*)&x[(size_t)(m0 + r) * 256 + kb * 64 + qq * 4];
                uint32_t h01, h23, l01, l23;
                split4(v, h01, h23, l01, l23);
                const uint32_t off = (uint32_t)r * 128 + (((uint32_t)qq * 8) ^ ((uint32_t)(r & 7) << 4));
                asm volatile("st.shared.v2.b32 [%0], {%1,%2};" :: "r"(ab + off), "r"(h01), "r"(h23) : "memory");
                asm volatile("st.shared.v2.b32 [%0], {%1,%2};" :: "r"(ab + 16384 + off), "r"(l01), "r"(l23) : "memory");
            }
            asm volatile("fence.proxy.async.shared::cta;" ::: "memory");
            MBARRIER_ARRIVE(AF(q));
        }
    }

    // ---------------- epilogue: 8 warps, column-split ----------------
    MBARRIER_WAIT_PARITY(MDN, 0);
    TCGEN05_FENCE_AFTER();

    if (wid < 8) {
        const int half = wid >> 2;           // 0: channels 0-127, 1: 128-255
        const int m    = (wid & 3) * 32 + lid;
        const int n    = n0 + m;
        float* __restrict__ orow = out + ((size_t)n * B_ + bb) * CH_;
        const float* __restrict__ aw = g_attw + bb * DW;
        const uint32_t tbase = tmem + half * 256;
        #pragma unroll 1
        for (int cc = 0; cc < 4; cc++) {
            uint32_t hr0[32], hr1[32];
            TCGEN05_LD_X32(hr0, tbase + cc * 32);          // radix 0 cols
            TCGEN05_LD_X32(hr1, tbase + 128 + cc * 32);    // radix 1 cols
            TCGEN05_WAIT_LD();
            #pragma unroll
            for (int q = 0; q < 8; q++) {
                const int ch = half * 128 + cc * 32 + q * 4;
                float4 b0 = *(const float4*)&b_conv[ch];
                float4 b1 = *(const float4*)&b_conv[256 + ch];
                float4 a0 = *(const float4*)&aw[ch];
                float4 a1 = *(const float4*)&aw[256 + ch];
                float4 o;
                o.x = a0.x * fmaxf(__uint_as_float(hr0[q*4+0]) + b0.x, 0.f)
                    + a1.x * fmaxf(__uint_as_float(hr1[q*4+0]) + b1.x, 0.f);
                o.y = a0.y * fmaxf(__uint_as_float(hr0[q*4+1]) + b0.y, 0.f)
                    + a1.y * fmaxf(__uint_as_float(hr1[q*4+1]) + b1.y, 0.f);
                o.z = a0.z * fmaxf(__uint_as_float(hr0[q*4+2]) + b0.z, 0.f)
                    + a1.z * fmaxf(__uint_as_float(hr1[q*4+2]) + b1.z, 0.f);
                o.w = a0.w * fmaxf(__uint_as_float(hr0[q*4+3]) + b0.w, 0.f)
                    + a1.w * fmaxf(__uint_as_float(hr1[q*4+3]) + b1.w, 0.f);
                *(float4*)(orow + ch) = o;
            }
        }
    }
    __syncthreads();
    if (wid == 0) { TCGEN05_DEALLOC(tmem, 512); TCGEN05_RELINQ(); }

#else  // ------------------- fp32 FFMA fallback (plain sm_103) --------------
    float (*As)[64]  = (float(*)[64])smem;
    float (*Bs)[516] = (float(*)[516])(smem + 16 * 64 * 4);

    const int trow = tid >> 6;
    const int tcol = tid & 63;
    const int aM = tid >> 2, aK = (tid & 3) << 2;
    const int bD = tid >> 2, bK = (tid & 3) << 2;

    for (int sub = 0; sub < 2; sub++) {
        const int ms = m0 + sub * 64;
        float acc[8][8];
        #pragma unroll
        for (int i = 0; i < 8; i++)
            #pragma unroll
            for (int jj = 0; jj < 8; jj++) acc[i][jj] = 0.f;

        float4 aReg = make_float4(0.f, 0.f, 0.f, 0.f);
        float4 bReg[4];
        if (tid < 256)
            aReg = *(const float4*)&x[(size_t)(ms + aM) * CIN + aK];
        #pragma unroll
        for (int p = 0; p < 4; p++)
            bReg[p] = *(const float4*)&w_conv[(size_t)(bD + p * 128) * CIN + bK];

        for (int ks = 0; ks < CIN; ks += 16) {
            __syncthreads();
            if (tid < 256) {
                As[aK + 0][aM] = aReg.x; As[aK + 1][aM] = aReg.y;
                As[aK + 2][aM] = aReg.z; As[aK + 3][aM] = aReg.w;
            }
            #pragma unroll
            for (int p = 0; p < 4; p++) {
                const int d = bD + p * 128;
                Bs[bK + 0][d] = bReg[p].x; Bs[bK + 1][d] = bReg[p].y;
                Bs[bK + 2][d] = bReg[p].z; Bs[bK + 3][d] = bReg[p].w;
            }
            __syncthreads();
            if (ks + 16 < CIN) {
                const int kn = ks + 16;
                if (tid < 256)
                    aReg = *(const float4*)&x[(size_t)(ms + aM) * CIN + kn + aK];
                #pragma unroll
                for (int p = 0; p < 4; p++)
                    bReg[p] = *(const float4*)&w_conv[(size_t)(bD + p * 128) * CIN + kn + bK];
            }
            #pragma unroll
            for (int k = 0; k < 16; k++) {
                float a[8], bf[8];
                *(float4*)&a[0]  = *(const float4*)&As[k][trow * 8];
                *(float4*)&a[4]  = *(const float4*)&As[k][trow * 8 + 4];
                *(float4*)&bf[0] = *(const float4*)&Bs[k][tcol * 4];
                *(float4*)&bf[4] = *(const float4*)&Bs[k][tcol * 4 + 256];
                #pragma unroll
                for (int i = 0; i < 8; i++)
                    #pragma unroll
                    for (int jj = 0; jj < 8; jj++)
                        acc[i][jj] += a[i] * bf[jj];
            }
        }
        __syncthreads();

        const int cbase = tcol * 4;
        float a0[4], a1[4], bias0[4], bias1[4];
        #pragma unroll
        for (int jj = 0; jj < 4; jj++) {
            a0[jj]    = g_attw[bb * DW + cbase + jj];
            a1[jj]    = g_attw[bb * DW + 256 + cbase + jj];
            bias0[jj] = b_conv[cbase + jj];
            bias1[jj] = b_conv[256 + cbase + jj];
        }
        #pragma unroll
        for (int i = 0; i < 8; i++) {
            const int n = n0 + sub * 64 + trow * 8 + i;
            float4 o;
            o.x = a0[0] * fmaxf(acc[i][0] + bias0[0], 0.f) + a1[0] * fmaxf(acc[i][4] + bias1[0], 0.f);
            o.y = a0[1] * fmaxf(acc[i][1] + bias0[1], 0.f) + a1[1] * fmaxf(acc[i][5] + bias1[1], 0.f);
            o.z = a0[2] * fmaxf(acc[i][2] + bias0[2], 0.f) + a1[2] * fmaxf(acc[i][6] + bias1[2], 0.f);
            o.w = a0[3] * fmaxf(acc[i][3] + bias0[3], 0.f) + a1[3] * fmaxf(acc[i][7] + bias1[3], 0.f);
            *(float4*)&out[((size_t)n * B_ + bb) * CH_ + cbase] = o;
        }
    }
#endif
}

extern "C" void kernel_launch(void* const* d_in, const int* in_sizes, int n_in,
                              void* d_out, int out_size) {
    const float* x      = (const float*)d_in[0];
    const float* w_conv = (const float*)d_in[1];
    const float* b_conv = (const float*)d_in[2];
    const float* w_fc1  = (const float*)d_in[3];
    const float* b_fc1  = (const float*)d_in[4];
    const float* w_fc2  = (const float*)d_in[5];
    // d_in[6] = b_fc2: cancels in the softmax-pair difference, unused.
    float* out = (float*)d_out;

    cudaFuncSetAttribute(gemm_kernel, cudaFuncAttributeMaxDynamicSharedMemorySize, SMEM_TOTAL);

    setup1_kernel<<<96, 512>>>(x, w_conv, b_conv);
    setup2_kernel<<<B_, 256>>>(w_fc1, b_fc1, w_fc2);
    gemm_kernel<<<(B_ * N_) / 128, 512, SMEM_TOTAL>>>(x, w_conv, b_conv, out);
}